// round 6
// baseline (speedup 1.0000x reference)
#include <cuda_runtime.h>
#include <math.h>

#define N_NODES 10000
#define N_EDGES 128000
#define E_HALF  64000

// ---------------- scratch (device globals; no allocations allowed) ----------------
__device__ float g_nf  [N_NODES*260];
__device__ float g_P   [N_NODES*128];
__device__ float g_x1  [N_NODES*64];
__device__ float g_x2  [N_NODES*64];
__device__ float g_x3  [N_NODES*64];
__device__ float g_x4  [N_NODES*64];
__device__ float g_Ebig[N_EDGES*128];
__device__ float g_M1  [N_EDGES*64];
__device__ float g_M2  [N_EDGES*64];
__device__ float g_M3  [N_EDGES*64];
__device__ float g_M4  [N_EDGES*64];
__device__ float g_H   [N_EDGES*64];
__device__ float g_Ep  [N_EDGES*64];
__device__ float g_W1n [260*128];
__device__ float g_Wbig[640*128];
__device__ float g_W2n [64*128];
__device__ float g_W3n [128*128];
__device__ float g_W4n [128*128];
__device__ float g_inv [N_NODES];
__device__ int   g_cnt [N_NODES];

// ---------------- generic SGEMM: C[M,BN] = op(A0|A1) @ B (+bias) ----------------
// A is logically [M, K0+K1], row-major via two source pointers (concat along K),
// optional relu on A reads. B row-major [K, >=BN] with leading dim ldB.
template<int BN>
__global__ __launch_bounds__(256) void gemm_kernel(
    const float* __restrict__ A0, int ldA0, int K0,
    const float* __restrict__ A1, int ldA1, int K1,
    int reluA,
    const float* __restrict__ B, int ldB,
    const float* __restrict__ bias,
    float* __restrict__ C, int ldC, int M)
{
    constexpr int BM = 128, BK = 16;
    constexpr int TM = 8, TN = BN / 16;
    __shared__ float As[BK][BM];
    __shared__ float Bs[BK][BN];

    const int tid = threadIdx.x;
    const int tx = tid & 15, ty = tid >> 4;
    const int m0 = blockIdx.x * BM;
    const int j0 = blockIdx.y * BN;
    const int K  = K0 + K1;

    float acc[TM][TN];
#pragma unroll
    for (int i = 0; i < TM; i++)
#pragma unroll
        for (int j = 0; j < TN; j++) acc[i][j] = 0.f;

    for (int k0 = 0; k0 < K; k0 += BK) {
        // ---- load A tile (each thread: 8 consecutive k of one row) ----
        {
            const int m = m0 + (tid >> 1);
            const int kb = (tid & 1) * 8;
#pragma unroll
            for (int i = 0; i < 8; i++) {
                const int kk = k0 + kb + i;
                float v = 0.f;
                if (m < M && kk < K) {
                    v = (kk < K0) ? A0[(long)m * ldA0 + kk]
                                  : A1[(long)m * ldA1 + (kk - K0)];
                    if (reluA) v = fmaxf(v, 0.f);
                }
                As[kb + i][tid >> 1] = v;
            }
        }
        // ---- load B tile ----
        {
            constexpr int ELEMS = BK * BN;
#pragma unroll
            for (int idx = tid; idx < ELEMS; idx += 256) {
                const int k = idx / BN, j = idx % BN;
                const int kk = k0 + k;
                Bs[k][j] = (kk < K) ? B[(long)kk * ldB + j0 + j] : 0.f;
            }
        }
        __syncthreads();
#pragma unroll
        for (int k = 0; k < BK; k++) {
            float a[TM], b[TN];
#pragma unroll
            for (int i = 0; i < TM; i++) a[i] = As[k][ty * TM + i];
#pragma unroll
            for (int j = 0; j < TN; j++) b[j] = Bs[k][tx * TN + j];
#pragma unroll
            for (int i = 0; i < TM; i++)
#pragma unroll
                for (int j = 0; j < TN; j++) acc[i][j] = fmaf(a[i], b[j], acc[i][j]);
        }
        __syncthreads();
    }
#pragma unroll
    for (int i = 0; i < TM; i++) {
        const int m = m0 + ty * TM + i;
        if (m >= M) continue;
#pragma unroll
        for (int j = 0; j < TN; j++) {
            const int jj = j0 + tx * TN + j;
            float v = acc[i][j];
            if (bias) v += bias[jj];
            C[(long)m * ldC + jj] = v;
        }
    }
}

// ---------------- misc elementwise kernels ----------------
__global__ void build_nf_kernel(const float* __restrict__ xorg,
                                const float* __restrict__ xrot)
{
    long idx = (long)blockIdx.x * blockDim.x + threadIdx.x;
    if (idx >= (long)N_NODES * 260) return;
    int n = (int)(idx / 260), k = (int)(idx % 260);
    g_nf[idx] = (k < 256) ? xorg[n * 256 + k] : xrot[n * 4 + (k - 256)];
}

// dst[k,128] : cols 0..63 <- srcA rows offA+k ; cols 64..127 <- srcB rows offB+k
__global__ void pack_kernel(float* __restrict__ dst,
                            const float* __restrict__ srcA, int offA,
                            const float* __restrict__ srcB, int offB, int K)
{
    int idx = blockIdx.x * blockDim.x + threadIdx.x;
    if (idx >= K * 128) return;
    int k = idx >> 7, j = idx & 127;
    dst[idx] = (j < 64) ? srcA[(offA + k) * 64 + j]
                        : srcB[(offB + k) * 64 + (j - 64)];
}

__global__ void zero_f_kernel(float* p, long n)
{
    long i = (long)blockIdx.x * blockDim.x + threadIdx.x;
    if (i < n) p[i] = 0.f;
}

__global__ void zero_cnt_kernel()
{
    int i = blockIdx.x * blockDim.x + threadIdx.x;
    if (i < N_NODES) g_cnt[i] = 0;
}

__global__ void count_kernel(const int* __restrict__ row)
{
    int e = blockIdx.x * blockDim.x + threadIdx.x;
    if (e < N_EDGES) atomicAdd(&g_cnt[row[e]], 1);
}

__global__ void invdeg_kernel()
{
    int n = blockIdx.x * blockDim.x + threadIdx.x;
    if (n < N_NODES) g_inv[n] = 1.f / fmaxf((float)g_cnt[n], 1.f);
}

// H[e,j] = relu( E0[e, offE0+j] (+E1[e,j]) + P[row,j] + P[col,64+j] + bias[j] (+rot·rotW) )
__global__ void combine_kernel(
    const int* __restrict__ row, const int* __restrict__ col,
    const float* __restrict__ P,
    const float* __restrict__ E0, int ldE0, int offE0,
    const float* __restrict__ E1,
    const float* __restrict__ bias,
    const float* __restrict__ rot, const float* __restrict__ rotW,
    float* __restrict__ H)
{
    int e = blockIdx.x * blockDim.y + threadIdx.y;
    int j = threadIdx.x;
    if (e >= N_EDGES) return;
    int r = row[e], c = col[e];
    float v = E0[(long)e * ldE0 + offE0 + j] + P[r * 128 + j] + P[c * 128 + 64 + j] + bias[j];
    if (E1) v += E1[(long)e * 64 + j];
    if (rot) {
#pragma unroll
        for (int kk = 0; kk < 4; kk++) v += rot[e * 4 + kk] * rotW[kk * 64 + j];
    }
    H[(long)e * 64 + j] = fmaxf(v, 0.f);
}

__global__ void scatter_kernel(const int* __restrict__ row,
                               const float* __restrict__ Msrc,
                               float* __restrict__ xsum)
{
    long tid = (long)blockIdx.x * blockDim.x + threadIdx.x;
    if (tid >= (long)N_EDGES * 64) return;
    int e = (int)(tid >> 6), j = (int)(tid & 63);
    atomicAdd(&xsum[row[e] * 64 + j], Msrc[tid]);
}

__global__ void finalize_kernel(float* __restrict__ x, int relu)
{
    long idx = (long)blockIdx.x * blockDim.x + threadIdx.x;
    if (idx >= (long)N_NODES * 64) return;
    int n = (int)(idx >> 6);
    float v = x[idx] * g_inv[n];
    x[idx] = relu ? fmaxf(v, 0.f) : v;
}

// out[n,0:4] = normalize(x4[n] @ lin1_w + lin1_b)
__global__ void node_head_kernel(const float* __restrict__ W,
                                 const float* __restrict__ b,
                                 float* __restrict__ out)
{
    int n = blockIdx.x * blockDim.x + threadIdx.x;
    if (n >= N_NODES) return;
    float y0 = b[0], y1 = b[1], y2 = b[2], y3 = b[3];
    const float* xr = g_x4 + (long)n * 64;
#pragma unroll 8
    for (int k = 0; k < 64; k++) {
        float xv = xr[k];
        y0 = fmaf(xv, W[k * 4 + 0], y0);
        y1 = fmaf(xv, W[k * 4 + 1], y1);
        y2 = fmaf(xv, W[k * 4 + 2], y2);
        y3 = fmaf(xv, W[k * 4 + 3], y3);
    }
    float s = y0 * y0 + y1 * y1 + y2 * y2 + y3 * y3;
    float nrm = fmaxf(sqrtf(s), 1e-12f);
    float r = 1.f / nrm;
    out[n * 4 + 0] = y0 * r;
    out[n * 4 + 1] = y1 * r;
    out[n * 4 + 2] = y2 * r;
    out[n * 4 + 3] = y3 * r;
}

// pred[e] = relu((M4[e]+M4[e+E/2]) @ W1 + b1) @ w2 + b2
__global__ __launch_bounds__(256) void edge_head_kernel(
    const float* __restrict__ W1, const float* __restrict__ b1,
    const float* __restrict__ w2, const float* __restrict__ b2,
    float* __restrict__ out)
{
    __shared__ float sW[64 * 32];
    __shared__ float sb[32];
    int tid = threadIdx.x;
    for (int i = tid; i < 64 * 32; i += 256) sW[i] = W1[i];
    if (tid < 32) sb[tid] = b1[tid];
    __syncthreads();
    int lane = tid & 31, w = tid >> 5;
    int e = blockIdx.x * 8 + w;
    if (e >= E_HALF) return;
    const float* h0 = g_M4 + (long)e * 64;
    const float* h1 = g_M4 + (long)(e + E_HALF) * 64;
    float t = sb[lane];
#pragma unroll 8
    for (int k = 0; k < 64; k++) {
        float h = h0[k] + h1[k];
        t = fmaf(h, sW[k * 32 + lane], t);
    }
    float r = fmaxf(t, 0.f) * w2[lane];
#pragma unroll
    for (int off = 16; off; off >>= 1) r += __shfl_down_sync(0xffffffffu, r, off);
    if (lane == 0) out[e] = r + b2[0];
}

// ---------------- host orchestration ----------------
template <class T>
static float* symaddr(T& s)
{
    void* p = nullptr;
    cudaGetSymbolAddress(&p, s);
    return (float*)p;
}

extern "C" void kernel_launch(void* const* d_in, const int* in_sizes, int n_in,
                              void* d_out, int out_size)
{
    (void)in_sizes; (void)n_in; (void)out_size;
    const float* x_org    = (const float*)d_in[0];
    const float* x_rot    = (const float*)d_in[1];
    const int*   eidx     = (const int*)  d_in[2];
    const float* eattr    = (const float*)d_in[3];
    const float* erot     = (const float*)d_in[4];
    const float* c1_w1 = (const float*)d_in[5];  const float* c1_b1 = (const float*)d_in[6];
    const float* c1_w2 = (const float*)d_in[7];  const float* c1_b2 = (const float*)d_in[8];
    const float* c2_w1 = (const float*)d_in[9];  const float* c2_b1 = (const float*)d_in[10];
    const float* c2_w2 = (const float*)d_in[11]; const float* c2_b2 = (const float*)d_in[12];
    const float* c3_w1 = (const float*)d_in[13]; const float* c3_b1 = (const float*)d_in[14];
    const float* c3_w2 = (const float*)d_in[15]; const float* c3_b2 = (const float*)d_in[16];
    const float* c4_w1 = (const float*)d_in[17]; const float* c4_b1 = (const float*)d_in[18];
    const float* c4_w2 = (const float*)d_in[19]; const float* c4_b2 = (const float*)d_in[20];
    const float* lin1_w = (const float*)d_in[21]; const float* lin1_b = (const float*)d_in[22];
    const float* efc_w1 = (const float*)d_in[23]; const float* efc_b1 = (const float*)d_in[24];
    const float* efc_w2 = (const float*)d_in[25]; const float* efc_b2 = (const float*)d_in[26];
    float* out = (float*)d_out;

    const int* row = eidx;
    const int* col = eidx + N_EDGES;

    float* nf   = symaddr(g_nf);
    float* P    = symaddr(g_P);
    float* x1   = symaddr(g_x1);
    float* x2   = symaddr(g_x2);
    float* x3   = symaddr(g_x3);
    float* x4   = symaddr(g_x4);
    float* Ebig = symaddr(g_Ebig);
    float* M1   = symaddr(g_M1);
    float* M2   = symaddr(g_M2);
    float* M3   = symaddr(g_M3);
    float* M4   = symaddr(g_M4);
    float* H    = symaddr(g_H);
    float* Ep   = symaddr(g_Ep);
    float* W1n  = symaddr(g_W1n);
    float* Wbig = symaddr(g_Wbig);
    float* W2n  = symaddr(g_W2n);
    float* W3n  = symaddr(g_W3n);
    float* W4n  = symaddr(g_W4n);

    const dim3 cdim(64, 4);
    const int CB = (N_EDGES + 3) / 4;                 // combine blocks
    const int GE = (N_EDGES + 127) / 128;             // gemm blocks over edges (1000)
    const int GN = (N_NODES + 127) / 128;             // gemm blocks over nodes (79)
    const int SB = (int)(((long)N_EDGES * 64 + 255) / 256); // scatter blocks
    const int ZB = (int)(((long)N_NODES * 64 + 255) / 256);

    // --- prep ---
    build_nf_kernel<<<(N_NODES * 260 + 255) / 256, 256>>>(x_org, x_rot);
    pack_kernel<<<(260 * 128 + 255) / 256, 256>>>(W1n,  c1_w1, 0,   c1_w1, 260, 260);
    pack_kernel<<<(640 * 128 + 255) / 256, 256>>>(Wbig, c1_w1, 520, c2_w1, 128, 640);
    pack_kernel<<<(64  * 128 + 255) / 256, 256>>>(W2n,  c2_w1, 0,   c2_w1, 64,  64);
    pack_kernel<<<(128 * 128 + 255) / 256, 256>>>(W3n,  c3_w1, 0,   c3_w1, 128, 128);
    pack_kernel<<<(128 * 128 + 255) / 256, 256>>>(W4n,  c4_w1, 0,   c4_w1, 128, 128);
    zero_cnt_kernel<<<(N_NODES + 255) / 256, 256>>>();
    count_kernel<<<(N_EDGES + 255) / 256, 256>>>(row);
    invdeg_kernel<<<(N_NODES + 255) / 256, 256>>>();

    // --- big fused edge GEMM: [E,640] @ [640,128] (conv1-edge | conv2-edge_attr) ---
    gemm_kernel<128><<<dim3(GE, 1), 256>>>(eattr, 640, 640, nullptr, 0, 0, 0,
                                           Wbig, 128, nullptr, Ebig, 128, N_EDGES);

    // ================= conv1 =================
    gemm_kernel<128><<<dim3(GN, 1), 256>>>(nf, 260, 260, nullptr, 0, 0, 0,
                                           W1n, 128, nullptr, P, 128, N_NODES);
    combine_kernel<<<CB, cdim>>>(row, col, P, Ebig, 128, 0, nullptr,
                                 c1_b1, erot, c1_w1 + 1160 * 64, H);
    gemm_kernel<64><<<dim3(GE, 1), 256>>>(H, 64, 64, nullptr, 0, 0, 0,
                                          c1_w2, 64, c1_b2, M1, 64, N_EDGES);
    zero_f_kernel<<<ZB, 256>>>(x1, (long)N_NODES * 64);
    scatter_kernel<<<SB, 256>>>(row, M1, x1);
    finalize_kernel<<<ZB, 256>>>(x1, 0);

    // ================= conv2 =================
    gemm_kernel<128><<<dim3(GN, 1), 256>>>(x1, 64, 64, nullptr, 0, 0, 0,
                                           W2n, 128, nullptr, P, 128, N_NODES);
    gemm_kernel<64><<<dim3(GE, 1), 256>>>(M1, 64, 64, nullptr, 0, 0, 1,
                                          c2_w1 + 768 * 64, 64, nullptr, Ep, 64, N_EDGES);
    combine_kernel<<<CB, cdim>>>(row, col, P, Ebig, 128, 64, Ep,
                                 c2_b1, nullptr, nullptr, H);
    gemm_kernel<64><<<dim3(GE, 1), 256>>>(H, 64, 64, nullptr, 0, 0, 0,
                                          c2_w2, 64, c2_b2, M2, 64, N_EDGES);
    zero_f_kernel<<<ZB, 256>>>(x2, (long)N_NODES * 64);
    scatter_kernel<<<SB, 256>>>(row, M2, x2);
    finalize_kernel<<<ZB, 256>>>(x2, 1);

    // ================= conv3 =================
    gemm_kernel<128><<<dim3(GN, 1), 256>>>(x2, 64, 64, x1, 64, 64, 0,
                                           W3n, 128, nullptr, P, 128, N_NODES);
    gemm_kernel<64><<<dim3(GE, 1), 256>>>(M2, 64, 64, M1, 64, 64, 1,
                                          c3_w1 + 256 * 64, 64, nullptr, Ep, 64, N_EDGES);
    combine_kernel<<<CB, cdim>>>(row, col, P, Ep, 64, 0, nullptr,
                                 c3_b1, nullptr, nullptr, H);
    gemm_kernel<64><<<dim3(GE, 1), 256>>>(H, 64, 64, nullptr, 0, 0, 0,
                                          c3_w2, 64, c3_b2, M3, 64, N_EDGES);
    zero_f_kernel<<<ZB, 256>>>(x3, (long)N_NODES * 64);
    scatter_kernel<<<SB, 256>>>(row, M3, x3);
    finalize_kernel<<<ZB, 256>>>(x3, 1);

    // ================= conv4 =================
    gemm_kernel<128><<<dim3(GN, 1), 256>>>(x3, 64, 64, x2, 64, 64, 0,
                                           W4n, 128, nullptr, P, 128, N_NODES);
    gemm_kernel<64><<<dim3(GE, 1), 256>>>(M3, 64, 64, M2, 64, 64, 1,
                                          c4_w1 + 256 * 64, 64, nullptr, Ep, 64, N_EDGES);
    combine_kernel<<<CB, cdim>>>(row, col, P, Ep, 64, 0, nullptr,
                                 c4_b1, nullptr, nullptr, H);
    gemm_kernel<64><<<dim3(GE, 1), 256>>>(H, 64, 64, nullptr, 0, 0, 0,
                                          c4_w2, 64, c4_b2, M4, 64, N_EDGES);
    zero_f_kernel<<<ZB, 256>>>(x4, (long)N_NODES * 64);
    scatter_kernel<<<SB, 256>>>(row, M4, x4);
    finalize_kernel<<<ZB, 256>>>(x4, 1);

    // ================= heads =================
    node_head_kernel<<<(N_NODES + 127) / 128, 128>>>(lin1_w, lin1_b, out);
    edge_head_kernel<<<(E_HALF + 7) / 8, 256>>>(efc_w1, efc_b1, efc_w2, efc_b2,
                                                out + N_NODES * 4);
}

// round 7
// speedup vs baseline: 1.2830x; 1.2830x over previous
#include <cuda_runtime.h>
#include <cuda_bf16.h>
#include <mma.h>
#include <math.h>

#define N_NODES 10000
#define N_EDGES 128000
#define E_HALF  64000

// ---------------- scratch (device globals; no allocations allowed) ----------------
__device__ float g_P   [N_NODES*128];
__device__ float g_x1  [N_NODES*64];
__device__ float g_x2  [N_NODES*64];
__device__ float g_x3  [N_NODES*64];
__device__ float g_x4  [N_NODES*64];
__device__ float g_Ebig[N_EDGES*128];
__device__ float g_M1  [N_EDGES*64];
__device__ float g_M2  [N_EDGES*64];
__device__ float g_M3  [N_EDGES*64];
__device__ float g_M4  [N_EDGES*64];
__device__ float g_H   [N_EDGES*64];
__device__ float g_W1n [260*128];
__device__ float g_Wbig[640*128];
__device__ float g_W2n [64*128];
__device__ float g_W3n [128*128];
__device__ float g_W4n [128*128];
__device__ float g_inv [N_NODES];
__device__ int   g_cnt [N_NODES];

// ---------------- split-bf16 helpers ----------------
__device__ __forceinline__ void split_store4(__nv_bfloat16* ph, __nv_bfloat16* pl, float4 v)
{
    float vv[4] = { v.x, v.y, v.z, v.w };
#pragma unroll
    for (int i = 0; i < 4; i++) {
        __nv_bfloat16 h = __float2bfloat16(vv[i]);
        ph[i] = h;
        pl[i] = __float2bfloat16(vv[i] - __bfloat162float(h));
    }
}

// =====================================================================
// Split-bf16 tensor-core GEMM:  C[M, N=BN*gridDim.y] = op(A0|A1) @ B
//   A logically [M, K0+K1] fp32 row-major via two pointers (concat on K),
//   optional relu on A. B fp32 row-major [K, ldB].
//   C ~= Ah@Bh + Ah@Bl + Al@Bh  (fp32 accumulate; ~1e-7 rel per product)
// EPI modes:
//   0: C = acc (+bias)                                  (node P GEMMs)
//   1: conv1-big: store Ebig (cols>=64); cols<64 -> H = relu(acc + Pgather + bias + rot@rotW)
//   2: H = relu(acc + Ebig[:,64+j] + Pgather + bias)    (conv2 hidden)
//   3: H = relu(acc + Pgather + bias)                   (conv3/4 hidden)
//   4: v = acc + bias; C = v; atomicAdd(xsum[row], v)   (M GEMM + scatter)
// =====================================================================
template<int BN, int EPI>
__global__ __launch_bounds__(256) void gemm_bf16(
    const float* __restrict__ A0, int ldA0, int K0,
    const float* __restrict__ A1, int ldA1, int K1, int reluA,
    const float* __restrict__ B, int ldB,
    const float* __restrict__ bias,
    float* __restrict__ C, int ldC, int M,
    const int* __restrict__ row, const int* __restrict__ col,
    const float* __restrict__ P, const float* __restrict__ E0,
    const float* __restrict__ rot, const float* __restrict__ rotW,
    float* __restrict__ xsum, float* __restrict__ Hout)
{
    using namespace nvcuda;
    constexpr int BM = 64, BK = 32;
    constexpr int WN = BN / 4;        // warp grid 2 x 4
    constexpr int MT = 2, NT = WN / 16;
    constexpr int TILE_BYTES = (2 * BM * BK + 2 * BK * BN) * 2;
    constexpr int CS_BYTES   = BM * BN * 4;
    constexpr int SMEM_BYTES = TILE_BYTES > CS_BYTES ? TILE_BYTES : CS_BYTES;

    __shared__ __align__(16) char sraw[SMEM_BYTES];
    __shared__ int sRow[BM], sCol[BM];
    __nv_bfloat16* Ah = (__nv_bfloat16*)sraw;
    __nv_bfloat16* Al = Ah + BM * BK;
    __nv_bfloat16* Bh = Al + BM * BK;
    __nv_bfloat16* Bl = Bh + BK * BN;
    float* Cs = (float*)sraw;

    const int tid  = threadIdx.x;
    const int warp = tid >> 5;
    const int wm   = warp >> 2, wn = warp & 3;
    const int m0   = blockIdx.x * BM;
    const int j0   = blockIdx.y * BN;
    const int K    = K0 + K1;

    if (EPI > 0) {
        if (tid < BM) {
            int e = m0 + tid;
            sRow[tid] = (e < M && row) ? row[e] : 0;
            sCol[tid] = (e < M && col) ? col[e] : 0;
        }
    }

    wmma::fragment<wmma::accumulator, 16, 16, 16, float> acc[MT][NT];
#pragma unroll
    for (int mi = 0; mi < MT; mi++)
#pragma unroll
        for (int ni = 0; ni < NT; ni++) wmma::fill_fragment(acc[mi][ni], 0.f);

    for (int kb = 0; kb < K; kb += BK) {
        // ---- A tile: 64 x 32 fp32 -> split bf16 (float4 loads; K0,K all %4==0) ----
        {
            const int r  = tid >> 2;
            const int m  = m0 + r;
            const int cb = (tid & 3) * 8;
#pragma unroll
            for (int q = 0; q < 2; q++) {
                const int c  = cb + q * 4;
                const int kk = kb + c;
                float4 v = make_float4(0.f, 0.f, 0.f, 0.f);
                if (m < M && kk < K) {
                    v = (kk < K0) ? *(const float4*)(A0 + (size_t)m * ldA0 + kk)
                                  : *(const float4*)(A1 + (size_t)m * ldA1 + (kk - K0));
                }
                if (reluA) {
                    v.x = fmaxf(v.x, 0.f); v.y = fmaxf(v.y, 0.f);
                    v.z = fmaxf(v.z, 0.f); v.w = fmaxf(v.w, 0.f);
                }
                split_store4(Ah + r * BK + c, Al + r * BK + c, v);
            }
        }
        // ---- B tile: 32 x BN ----
        {
            constexpr int JP = BN / 4;
#pragma unroll
            for (int t = 0; t < (BK * JP) / 256; t++) {
                const int idx = tid + t * 256;
                const int k = idx / JP, jc = idx % JP;
                const int kk = kb + k;
                float4 v = make_float4(0.f, 0.f, 0.f, 0.f);
                if (kk < K) v = *(const float4*)(B + (size_t)kk * ldB + j0 + jc * 4);
                split_store4(Bh + k * BN + jc * 4, Bl + k * BN + jc * 4, v);
            }
        }
        __syncthreads();
#pragma unroll
        for (int ks = 0; ks < 2; ks++) {
            wmma::fragment<wmma::matrix_a, 16, 16, 16, __nv_bfloat16, wmma::row_major> fah[MT], fal[MT];
            wmma::fragment<wmma::matrix_b, 16, 16, 16, __nv_bfloat16, wmma::row_major> fbh[NT], fbl[NT];
#pragma unroll
            for (int mi = 0; mi < MT; mi++) {
                const int off = (wm * 32 + mi * 16) * BK + ks * 16;
                wmma::load_matrix_sync(fah[mi], Ah + off, BK);
                wmma::load_matrix_sync(fal[mi], Al + off, BK);
            }
#pragma unroll
            for (int ni = 0; ni < NT; ni++) {
                const int off = (ks * 16) * BN + wn * WN + ni * 16;
                wmma::load_matrix_sync(fbh[ni], Bh + off, BN);
                wmma::load_matrix_sync(fbl[ni], Bl + off, BN);
            }
#pragma unroll
            for (int mi = 0; mi < MT; mi++)
#pragma unroll
                for (int ni = 0; ni < NT; ni++) {
                    wmma::mma_sync(acc[mi][ni], fah[mi], fbh[ni], acc[mi][ni]);
                    wmma::mma_sync(acc[mi][ni], fah[mi], fbl[ni], acc[mi][ni]);
                    wmma::mma_sync(acc[mi][ni], fal[mi], fbh[ni], acc[mi][ni]);
                }
        }
        __syncthreads();
    }

    // ---- epilogue via smem C tile (tiles are dead; reuse sraw) ----
#pragma unroll
    for (int mi = 0; mi < MT; mi++)
#pragma unroll
        for (int ni = 0; ni < NT; ni++)
            wmma::store_matrix_sync(Cs + (wm * 32 + mi * 16) * BN + wn * WN + ni * 16,
                                    acc[mi][ni], BN, wmma::mem_row_major);
    __syncthreads();

    for (int idx = tid; idx < BM * BN; idx += 256) {
        const int i = idx / BN, j = idx - i * BN;
        const int m = m0 + i;
        if (m >= M) continue;
        const int jg = j0 + j;
        float v = Cs[idx];
        if (EPI == 0) {
            if (bias) v += bias[jg];
            C[(size_t)m * ldC + jg] = v;
        } else if (EPI == 1) {
            if (j >= 64) {
                C[(size_t)m * ldC + jg] = v;      // Ebig upper half (conv2 input)
            } else {
                const int r = sRow[i], c = sCol[i];
                float h = v + P[r * 128 + j] + P[c * 128 + 64 + j] + bias[j];
#pragma unroll
                for (int kk = 0; kk < 4; kk++)
                    h += rot[(size_t)m * 4 + kk] * rotW[kk * 64 + j];
                Hout[(size_t)m * 64 + j] = fmaxf(h, 0.f);
            }
        } else if (EPI == 2 || EPI == 3) {
            const int r = sRow[i], c = sCol[i];
            float h = v + P[r * 128 + j] + P[c * 128 + 64 + j] + bias[j];
            if (EPI == 2) h += E0[(size_t)m * 128 + 64 + j];
            C[(size_t)m * 64 + j] = fmaxf(h, 0.f);
        } else { // EPI == 4
            v += bias[j];
            C[(size_t)m * 64 + j] = v;
            atomicAdd(&xsum[sRow[i] * 64 + j], v);
        }
    }
}

// ---------------- misc elementwise kernels ----------------
// dst[k,128] : cols 0..63 <- srcA rows offA+k ; cols 64..127 <- srcB rows offB+k
__global__ void pack_kernel(float* __restrict__ dst,
                            const float* __restrict__ srcA, int offA,
                            const float* __restrict__ srcB, int offB, int K)
{
    int idx = blockIdx.x * blockDim.x + threadIdx.x;
    if (idx >= K * 128) return;
    int k = idx >> 7, j = idx & 127;
    dst[idx] = (j < 64) ? srcA[(offA + k) * 64 + j]
                        : srcB[(offB + k) * 64 + (j - 64)];
}

__global__ void zero_f_kernel(float* p, long n)
{
    long i = (long)blockIdx.x * blockDim.x + threadIdx.x;
    if (i < n) p[i] = 0.f;
}

__global__ void zero_cnt_kernel()
{
    int i = blockIdx.x * blockDim.x + threadIdx.x;
    if (i < N_NODES) g_cnt[i] = 0;
}

__global__ void count_kernel(const int* __restrict__ row)
{
    int e = blockIdx.x * blockDim.x + threadIdx.x;
    if (e < N_EDGES) atomicAdd(&g_cnt[row[e]], 1);
}

__global__ void invdeg_kernel()
{
    int n = blockIdx.x * blockDim.x + threadIdx.x;
    if (n < N_NODES) g_inv[n] = 1.f / fmaxf((float)g_cnt[n], 1.f);
}

__global__ void finalize_kernel(float* __restrict__ x, int relu)
{
    long idx = (long)blockIdx.x * blockDim.x + threadIdx.x;
    if (idx >= (long)N_NODES * 64) return;
    int n = (int)(idx >> 6);
    float v = x[idx] * g_inv[n];
    x[idx] = relu ? fmaxf(v, 0.f) : v;
}

// out[n,0:4] = normalize(x4[n] @ lin1_w + lin1_b)
__global__ void node_head_kernel(const float* __restrict__ W,
                                 const float* __restrict__ b,
                                 float* __restrict__ out)
{
    int n = blockIdx.x * blockDim.x + threadIdx.x;
    if (n >= N_NODES) return;
    float y0 = b[0], y1 = b[1], y2 = b[2], y3 = b[3];
    const float* xr = g_x4 + (long)n * 64;
#pragma unroll 8
    for (int k = 0; k < 64; k++) {
        float xv = xr[k];
        y0 = fmaf(xv, W[k * 4 + 0], y0);
        y1 = fmaf(xv, W[k * 4 + 1], y1);
        y2 = fmaf(xv, W[k * 4 + 2], y2);
        y3 = fmaf(xv, W[k * 4 + 3], y3);
    }
    float s = y0 * y0 + y1 * y1 + y2 * y2 + y3 * y3;
    float r = 1.f / fmaxf(sqrtf(s), 1e-12f);
    out[n * 4 + 0] = y0 * r;
    out[n * 4 + 1] = y1 * r;
    out[n * 4 + 2] = y2 * r;
    out[n * 4 + 3] = y3 * r;
}

// pred[e] = relu((M4[e]+M4[e+E/2]) @ W1 + b1) @ w2 + b2
__global__ __launch_bounds__(256) void edge_head_kernel(
    const float* __restrict__ W1, const float* __restrict__ b1,
    const float* __restrict__ w2, const float* __restrict__ b2,
    float* __restrict__ out)
{
    __shared__ float sW[64 * 32];
    __shared__ float sb[32];
    int tid = threadIdx.x;
    for (int i = tid; i < 64 * 32; i += 256) sW[i] = W1[i];
    if (tid < 32) sb[tid] = b1[tid];
    __syncthreads();
    int lane = tid & 31, w = tid >> 5;
    int e = blockIdx.x * 8 + w;
    if (e >= E_HALF) return;
    const float* h0 = g_M4 + (long)e * 64;
    const float* h1 = g_M4 + (long)(e + E_HALF) * 64;
    float t = sb[lane];
#pragma unroll 8
    for (int k = 0; k < 64; k++) {
        float h = h0[k] + h1[k];
        t = fmaf(h, sW[k * 32 + lane], t);
    }
    float r = fmaxf(t, 0.f) * w2[lane];
#pragma unroll
    for (int off = 16; off; off >>= 1) r += __shfl_down_sync(0xffffffffu, r, off);
    if (lane == 0) out[e] = r + b2[0];
}

// ---------------- host orchestration ----------------
template <class T>
static float* symaddr(T& s)
{
    void* p = nullptr;
    cudaGetSymbolAddress(&p, s);
    return (float*)p;
}

extern "C" void kernel_launch(void* const* d_in, const int* in_sizes, int n_in,
                              void* d_out, int out_size)
{
    (void)in_sizes; (void)n_in; (void)out_size;
    const float* x_org = (const float*)d_in[0];
    const float* x_rot = (const float*)d_in[1];
    const int*   eidx  = (const int*)  d_in[2];
    const float* eattr = (const float*)d_in[3];
    const float* erot  = (const float*)d_in[4];
    const float* c1_w1 = (const float*)d_in[5];  const float* c1_b1 = (const float*)d_in[6];
    const float* c1_w2 = (const float*)d_in[7];  const float* c1_b2 = (const float*)d_in[8];
    const float* c2_w1 = (const float*)d_in[9];  const float* c2_b1 = (const float*)d_in[10];
    const float* c2_w2 = (const float*)d_in[11]; const float* c2_b2 = (const float*)d_in[12];
    const float* c3_w1 = (const float*)d_in[13]; const float* c3_b1 = (const float*)d_in[14];
    const float* c3_w2 = (const float*)d_in[15]; const float* c3_b2 = (const float*)d_in[16];
    const float* c4_w1 = (const float*)d_in[17]; const float* c4_b1 = (const float*)d_in[18];
    const float* c4_w2 = (const float*)d_in[19]; const float* c4_b2 = (const float*)d_in[20];
    const float* lin1_w = (const float*)d_in[21]; const float* lin1_b = (const float*)d_in[22];
    const float* efc_w1 = (const float*)d_in[23]; const float* efc_b1 = (const float*)d_in[24];
    const float* efc_w2 = (const float*)d_in[25]; const float* efc_b2 = (const float*)d_in[26];
    float* out = (float*)d_out;

    const int* row = eidx;
    const int* col = eidx + N_EDGES;

    float* P    = symaddr(g_P);
    float* x1   = symaddr(g_x1);
    float* x2   = symaddr(g_x2);
    float* x3   = symaddr(g_x3);
    float* x4   = symaddr(g_x4);
    float* Ebig = symaddr(g_Ebig);
    float* M1   = symaddr(g_M1);
    float* M2   = symaddr(g_M2);
    float* M3   = symaddr(g_M3);
    float* M4   = symaddr(g_M4);
    float* H    = symaddr(g_H);
    float* W1n  = symaddr(g_W1n);
    float* Wbig = symaddr(g_Wbig);
    float* W2n  = symaddr(g_W2n);
    float* W3n  = symaddr(g_W3n);
    float* W4n  = symaddr(g_W4n);

    const int GE = N_EDGES / 64;               // 2000
    const int GN = (N_NODES + 63) / 64;        // 157
    const int ZB = (int)(((long)N_NODES * 64 + 255) / 256);
    const float* NF = nullptr;
    const int*   NI = nullptr;

    // --- prep ---
    pack_kernel<<<(260 * 128 + 255) / 256, 256>>>(W1n,  c1_w1, 0,   c1_w1, 260, 260);
    pack_kernel<<<(640 * 128 + 255) / 256, 256>>>(Wbig, c1_w1, 520, c2_w1, 128, 640);
    pack_kernel<<<(64  * 128 + 255) / 256, 256>>>(W2n,  c2_w1, 0,   c2_w1, 64,  64);
    pack_kernel<<<(128 * 128 + 255) / 256, 256>>>(W3n,  c3_w1, 0,   c3_w1, 128, 128);
    pack_kernel<<<(128 * 128 + 255) / 256, 256>>>(W4n,  c4_w1, 0,   c4_w1, 128, 128);
    zero_cnt_kernel<<<(N_NODES + 255) / 256, 256>>>();
    count_kernel<<<(N_EDGES + 255) / 256, 256>>>(row);
    invdeg_kernel<<<(N_NODES + 255) / 256, 256>>>();
    zero_f_kernel<<<ZB, 256>>>(x1, (long)N_NODES * 64);
    zero_f_kernel<<<ZB, 256>>>(x2, (long)N_NODES * 64);
    zero_f_kernel<<<ZB, 256>>>(x3, (long)N_NODES * 64);
    zero_f_kernel<<<ZB, 256>>>(x4, (long)N_NODES * 64);

    // ================= conv1 =================
    gemm_bf16<128, 0><<<GN, 256>>>(x_org, 256, 256, x_rot, 4, 4, 0,
                                   W1n, 128, NF, P, 128, N_NODES,
                                   NI, NI, NF, NF, NF, NF, nullptr, nullptr);
    // big fused: Ebig = eattr @ Wbig ; H1 = relu(Ebig[:,:64] + Pgather + b1 + rot@rotW)
    gemm_bf16<128, 1><<<GE, 256>>>(eattr, 640, 640, NF, 0, 0, 0,
                                   Wbig, 128, c1_b1, Ebig, 128, N_EDGES,
                                   row, col, P, NF, erot, c1_w1 + 1160 * 64, nullptr, H);
    gemm_bf16<64, 4><<<GE, 256>>>(H, 64, 64, NF, 0, 0, 0,
                                  c1_w2, 64, c1_b2, M1, 64, N_EDGES,
                                  row, NI, NF, NF, NF, NF, x1, nullptr);
    finalize_kernel<<<ZB, 256>>>(x1, 0);

    // ================= conv2 =================
    gemm_bf16<128, 0><<<GN, 256>>>(x1, 64, 64, NF, 0, 0, 0,
                                   W2n, 128, NF, P, 128, N_NODES,
                                   NI, NI, NF, NF, NF, NF, nullptr, nullptr);
    gemm_bf16<64, 2><<<GE, 256>>>(M1, 64, 64, NF, 0, 0, 1,
                                  c2_w1 + 768 * 64, 64, c2_b1, H, 64, N_EDGES,
                                  row, col, P, Ebig, NF, NF, nullptr, nullptr);
    gemm_bf16<64, 4><<<GE, 256>>>(H, 64, 64, NF, 0, 0, 0,
                                  c2_w2, 64, c2_b2, M2, 64, N_EDGES,
                                  row, NI, NF, NF, NF, NF, x2, nullptr);
    finalize_kernel<<<ZB, 256>>>(x2, 1);

    // ================= conv3 =================
    gemm_bf16<128, 0><<<GN, 256>>>(x2, 64, 64, x1, 64, 64, 0,
                                   W3n, 128, NF, P, 128, N_NODES,
                                   NI, NI, NF, NF, NF, NF, nullptr, nullptr);
    gemm_bf16<64, 3><<<GE, 256>>>(M2, 64, 64, M1, 64, 64, 1,
                                  c3_w1 + 256 * 64, 64, c3_b1, H, 64, N_EDGES,
                                  row, col, P, NF, NF, NF, nullptr, nullptr);
    gemm_bf16<64, 4><<<GE, 256>>>(H, 64, 64, NF, 0, 0, 0,
                                  c3_w2, 64, c3_b2, M3, 64, N_EDGES,
                                  row, NI, NF, NF, NF, NF, x3, nullptr);
    finalize_kernel<<<ZB, 256>>>(x3, 1);

    // ================= conv4 =================
    gemm_bf16<128, 0><<<GN, 256>>>(x3, 64, 64, x2, 64, 64, 0,
                                   W4n, 128, NF, P, 128, N_NODES,
                                   NI, NI, NF, NF, NF, NF, nullptr, nullptr);
    gemm_bf16<64, 3><<<GE, 256>>>(M3, 64, 64, M2, 64, 64, 1,
                                  c4_w1 + 256 * 64, 64, c4_b1, H, 64, N_EDGES,
                                  row, col, P, NF, NF, NF, nullptr, nullptr);
    gemm_bf16<64, 4><<<GE, 256>>>(H, 64, 64, NF, 0, 0, 0,
                                  c4_w2, 64, c4_b2, M4, 64, N_EDGES,
                                  row, NI, NF, NF, NF, NF, x4, nullptr);
    finalize_kernel<<<ZB, 256>>>(x4, 1);

    // ================= heads =================
    node_head_kernel<<<(N_NODES + 127) / 128, 128>>>(lin1_w, lin1_b, out);
    edge_head_kernel<<<(E_HALF + 7) / 8, 256>>>(efc_w1, efc_b1, efc_w2, efc_b2,
                                                out + N_NODES * 4);
}